// round 1
// baseline (speedup 1.0000x reference)
#include <cuda_runtime.h>

// Problem constants (fixed by reference setup_inputs)
#define D_MODEL   512
#define NUM_HEADS 8
#define HEAD_DIM  64
#define SEQ       2048
#define BATCH     4
#define M_TOTAL   (BATCH * SEQ)   // 8192

// Scratch for projected Q/K/V (fp32). Static __device__ arrays are the
// allowed scratch mechanism (no runtime allocation).
__device__ float g_qp[M_TOTAL * D_MODEL];
__device__ float g_kp[M_TOTAL * D_MODEL];
__device__ float g_vp[M_TOTAL * D_MODEL];

// ---------------------------------------------------------------------------
// Kernel 1: projection GEMM  C = A @ W^T + b
// A: [M, 512] row-major, W: [512, 512] row-major (both K-contiguous).
// Tile: 128x128, BK=16, 256 threads, 8x8 register microtile.
// blockIdx.z selects Q / K / V.
// ---------------------------------------------------------------------------
__global__ __launch_bounds__(256, 2)
void proj_kernel(const float* __restrict__ Aq, const float* __restrict__ Ak,
                 const float* __restrict__ Av,
                 const float* __restrict__ Wq, const float* __restrict__ bq,
                 const float* __restrict__ Wk, const float* __restrict__ bk,
                 const float* __restrict__ Wv, const float* __restrict__ bv)
{
    const float* A; const float* W; const float* bias; float* C;
    if (blockIdx.z == 0)      { A = Aq; W = Wq; bias = bq; C = g_qp; }
    else if (blockIdx.z == 1) { A = Ak; W = Wk; bias = bk; C = g_kp; }
    else                      { A = Av; W = Wv; bias = bv; C = g_vp; }

    __shared__ float As[16][132];   // [k][m], padded to reduce store conflicts
    __shared__ float Ws[16][132];   // [k][n]

    const int t  = threadIdx.x;
    const int tm = t >> 4;          // 0..15
    const int tn = t & 15;          // 0..15
    const int m0 = blockIdx.y * 128;
    const int n0 = blockIdx.x * 128;

    float acc[8][8];
    #pragma unroll
    for (int i = 0; i < 8; i++)
        #pragma unroll
        for (int j = 0; j < 8; j++) acc[i][j] = 0.f;

    for (int kt = 0; kt < D_MODEL; kt += 16) {
        #pragma unroll
        for (int q2 = 0; q2 < 2; q2++) {
            int l4  = t + q2 * 256;          // 0..511 float4 slots
            int row = l4 >> 2;               // 0..127
            int c4  = (l4 & 3) << 2;         // 0,4,8,12
            float4 av = *(const float4*)&A[(size_t)(m0 + row) * D_MODEL + kt + c4];
            As[c4 + 0][row] = av.x; As[c4 + 1][row] = av.y;
            As[c4 + 2][row] = av.z; As[c4 + 3][row] = av.w;
            float4 wv = *(const float4*)&W[(size_t)(n0 + row) * D_MODEL + kt + c4];
            Ws[c4 + 0][row] = wv.x; Ws[c4 + 1][row] = wv.y;
            Ws[c4 + 2][row] = wv.z; Ws[c4 + 3][row] = wv.w;
        }
        __syncthreads();

        #pragma unroll
        for (int kk = 0; kk < 16; kk++) {
            float a[8], w[8];
            *(float4*)&a[0] = *(const float4*)&As[kk][tm * 8];
            *(float4*)&a[4] = *(const float4*)&As[kk][tm * 8 + 4];
            *(float4*)&w[0] = *(const float4*)&Ws[kk][tn * 8];
            *(float4*)&w[4] = *(const float4*)&Ws[kk][tn * 8 + 4];
            #pragma unroll
            for (int i = 0; i < 8; i++)
                #pragma unroll
                for (int j = 0; j < 8; j++)
                    acc[i][j] = fmaf(a[i], w[j], acc[i][j]);
        }
        __syncthreads();
    }

    // epilogue: + bias, vectorized store
    float bv8[8];
    *(float4*)&bv8[0] = *(const float4*)&bias[n0 + tn * 8];
    *(float4*)&bv8[4] = *(const float4*)&bias[n0 + tn * 8 + 4];
    #pragma unroll
    for (int i = 0; i < 8; i++) {
        size_t m = (size_t)(m0 + tm * 8 + i);
        float4 o0 = make_float4(acc[i][0] + bv8[0], acc[i][1] + bv8[1],
                                acc[i][2] + bv8[2], acc[i][3] + bv8[3]);
        float4 o1 = make_float4(acc[i][4] + bv8[4], acc[i][5] + bv8[5],
                                acc[i][6] + bv8[6], acc[i][7] + bv8[7]);
        *(float4*)&C[m * D_MODEL + n0 + tn * 8]     = o0;
        *(float4*)&C[m * D_MODEL + n0 + tn * 8 + 4] = o1;
    }
}

// ---------------------------------------------------------------------------
// Kernel 2: fused flash attention (fp32, online softmax)
// One block per (b, h, 64-query tile). 256 threads, each owns a 4x4 microtile.
// Smem (dynamic, 69632 B):
//   Qt [d][i]  (64x68)  - Q transposed, loaded once
//   Kt [d][j]  (64x68)  - K transposed, per key tile
//   Vs [j][d]  (64x68)  - V, per key tile
//   Pt [j][i]  (64x68)  - softmax probs transposed, per key tile
// ---------------------------------------------------------------------------
#define FPAD 68
#define FLASH_SMEM (4 * 64 * FPAD * 4)

__global__ __launch_bounds__(256)
void flash_kernel(float* __restrict__ out)
{
    extern __shared__ float sm[];
    float* Qt = sm;
    float* Kt = sm + 64 * FPAD;
    float* Vs = sm + 2 * 64 * FPAD;
    float* Pt = sm + 3 * 64 * FPAD;

    const int t  = threadIdx.x;
    const int ti = t >> 4;   // 0..15 : query-row group
    const int tj = t & 15;   // 0..15 : key/col group
    const int q0 = blockIdx.x * 64;
    const int h  = blockIdx.y;
    const int b  = blockIdx.z;
    const size_t base = (size_t)b * SEQ * D_MODEL + (size_t)h * HEAD_DIM;

    // ---- load Q tile transposed (once per block) ----
    #pragma unroll
    for (int it = 0; it < 4; it++) {
        int l4 = t + it * 256;          // 0..1023 float4 slots
        int i  = l4 >> 4;               // 0..63 query row
        int d4 = (l4 & 15) << 2;        // 0,4,...,60
        float4 v = *(const float4*)&g_qp[base + (size_t)(q0 + i) * D_MODEL + d4];
        Qt[(d4 + 0) * FPAD + i] = v.x; Qt[(d4 + 1) * FPAD + i] = v.y;
        Qt[(d4 + 2) * FPAD + i] = v.z; Qt[(d4 + 3) * FPAD + i] = v.w;
    }

    float o[4][4];
    #pragma unroll
    for (int a = 0; a < 4; a++)
        #pragma unroll
        for (int c = 0; c < 4; c++) o[a][c] = 0.f;
    float mrow[4] = {-1e30f, -1e30f, -1e30f, -1e30f};
    float lrow[4] = {0.f, 0.f, 0.f, 0.f};

    for (int nt = 0; nt < SEQ / 64; nt++) {
        const int k0 = nt * 64;
        // ---- load K (transposed) and V tiles ----
        #pragma unroll
        for (int it = 0; it < 4; it++) {
            int l4 = t + it * 256;
            int j  = l4 >> 4;
            int d4 = (l4 & 15) << 2;
            float4 kv = *(const float4*)&g_kp[base + (size_t)(k0 + j) * D_MODEL + d4];
            Kt[(d4 + 0) * FPAD + j] = kv.x; Kt[(d4 + 1) * FPAD + j] = kv.y;
            Kt[(d4 + 2) * FPAD + j] = kv.z; Kt[(d4 + 3) * FPAD + j] = kv.w;
            float4 vv = *(const float4*)&g_vp[base + (size_t)(k0 + j) * D_MODEL + d4];
            *(float4*)&Vs[j * FPAD + d4] = vv;
        }
        __syncthreads();

        // ---- S = (Q K^T) * scale ----
        float s[4][4];
        #pragma unroll
        for (int a = 0; a < 4; a++)
            #pragma unroll
            for (int c = 0; c < 4; c++) s[a][c] = 0.f;

        #pragma unroll 8
        for (int d = 0; d < 64; d++) {
            float q4[4], k4[4];
            *(float4*)q4 = *(const float4*)&Qt[d * FPAD + ti * 4];
            *(float4*)k4 = *(const float4*)&Kt[d * FPAD + tj * 4];
            #pragma unroll
            for (int a = 0; a < 4; a++)
                #pragma unroll
                for (int c = 0; c < 4; c++)
                    s[a][c] = fmaf(q4[a], k4[c], s[a][c]);
        }

        // ---- online softmax (row reductions across the 16 tj lanes) ----
        #pragma unroll
        for (int a = 0; a < 4; a++) {
            #pragma unroll
            for (int c = 0; c < 4; c++) s[a][c] *= 0.125f;  // 1/sqrt(64)
            float tmax = fmaxf(fmaxf(s[a][0], s[a][1]), fmaxf(s[a][2], s[a][3]));
            #pragma unroll
            for (int off = 8; off > 0; off >>= 1)
                tmax = fmaxf(tmax, __shfl_xor_sync(0xffffffffu, tmax, off));
            float newm  = fmaxf(mrow[a], tmax);
            float alpha = __expf(mrow[a] - newm);
            mrow[a] = newm;
            float rsum = 0.f;
            #pragma unroll
            for (int c = 0; c < 4; c++) {
                s[a][c] = __expf(s[a][c] - newm);  // s becomes P
                rsum += s[a][c];
            }
            #pragma unroll
            for (int off = 8; off > 0; off >>= 1)
                rsum += __shfl_xor_sync(0xffffffffu, rsum, off);
            lrow[a] = lrow[a] * alpha + rsum;
            #pragma unroll
            for (int c = 0; c < 4; c++) o[a][c] *= alpha;
        }

        // ---- stage P transposed: Pt[j][i], vectorized along i ----
        #pragma unroll
        for (int c = 0; c < 4; c++) {
            float4 pv = make_float4(s[0][c], s[1][c], s[2][c], s[3][c]);
            *(float4*)&Pt[(tj * 4 + c) * FPAD + ti * 4] = pv;
        }
        __syncthreads();

        // ---- O += P @ V ----
        #pragma unroll 8
        for (int j = 0; j < 64; j++) {
            float p4[4], v4[4];
            *(float4*)p4 = *(const float4*)&Pt[j * FPAD + ti * 4];
            *(float4*)v4 = *(const float4*)&Vs[j * FPAD + tj * 4];
            #pragma unroll
            for (int a = 0; a < 4; a++)
                #pragma unroll
                for (int c = 0; c < 4; c++)
                    o[a][c] = fmaf(p4[a], v4[c], o[a][c]);
        }
        __syncthreads();
    }

    // ---- normalize + store ----
    #pragma unroll
    for (int a = 0; a < 4; a++) {
        float inv = 1.f / lrow[a];
        float4 ov = make_float4(o[a][0] * inv, o[a][1] * inv,
                                o[a][2] * inv, o[a][3] * inv);
        *(float4*)&out[base + (size_t)(q0 + ti * 4 + a) * D_MODEL + tj * 4] = ov;
    }
}

// ---------------------------------------------------------------------------
// Launch
// ---------------------------------------------------------------------------
extern "C" void kernel_launch(void* const* d_in, const int* in_sizes, int n_in,
                              void* d_out, int out_size)
{
    const float* q  = (const float*)d_in[0];
    const float* k  = (const float*)d_in[1];
    const float* v  = (const float*)d_in[2];
    const float* Wq = (const float*)d_in[3];
    const float* bq = (const float*)d_in[4];
    const float* Wk = (const float*)d_in[5];
    const float* bk = (const float*)d_in[6];
    const float* Wv = (const float*)d_in[7];
    const float* bv = (const float*)d_in[8];
    float* out = (float*)d_out;

    cudaFuncSetAttribute(flash_kernel,
                         cudaFuncAttributeMaxDynamicSharedMemorySize, FLASH_SMEM);

    dim3 gproj(D_MODEL / 128, M_TOTAL / 128, 3);
    proj_kernel<<<gproj, 256>>>(q, k, v, Wq, bq, Wk, bk, Wv, bv);

    dim3 gflash(SEQ / 64, NUM_HEADS, BATCH);
    flash_kernel<<<gflash, 256, FLASH_SMEM>>>(out);
}

// round 4
// speedup vs baseline: 2.1414x; 2.1414x over previous
#include <cuda_runtime.h>
#include <cuda_bf16.h>
#include <cstdint>

#define D_MODEL   512
#define NUM_HEADS 8
#define HEAD_DIM  64
#define SEQ       2048
#define BATCH     4
#define M_TOTAL   (BATCH * SEQ)          // 8192
#define IN_ELEMS  (M_TOTAL * D_MODEL)    // 4194304
#define W_ELEMS   (D_MODEL * D_MODEL)

// ---------------------------------------------------------------------------
// Scratch (static __device__ = allowed)
// ---------------------------------------------------------------------------
__device__ __nv_bfloat16 g_inh[3][IN_ELEMS], g_inl[3][IN_ELEMS];
__device__ __nv_bfloat16 g_Wh3[3][W_ELEMS], g_Wl3[3][W_ELEMS];
// projected, head-major: idx = (h*M_TOTAL + m)*64 + d
__device__ __nv_bfloat16 g_Qh[IN_ELEMS], g_Ql[IN_ELEMS];
__device__ __nv_bfloat16 g_Kh[IN_ELEMS], g_Kl[IN_ELEMS];
__device__ __nv_bfloat16 g_Vh[IN_ELEMS], g_Vl[IN_ELEMS];

// ---------------------------------------------------------------------------
// Helpers
// ---------------------------------------------------------------------------
__device__ __forceinline__ uint32_t smem_u32(const void* p) {
    uint32_t a;
    asm("{ .reg .u64 t; cvta.to.shared.u64 t, %1; cvt.u32.u64 %0, t; }"
        : "=r"(a) : "l"(p));
    return a;
}
// SW128-style swizzled byte offset; tiles have 64-bf16 (128B) rows
__device__ __forceinline__ uint32_t swzo(int row, int col) {
    uint32_t bo = (uint32_t)row * 128u + (uint32_t)col * 2u;
    return bo ^ ((bo >> 3) & 0x70u);
}
#define LDSM4(R, a)                                                            \
    asm volatile("ldmatrix.sync.aligned.m8n8.x4.shared.b16 {%0,%1,%2,%3}, [%4];" \
        : "=r"((R)[0]), "=r"((R)[1]), "=r"((R)[2]), "=r"((R)[3]) : "r"(a))
#define LDSM4T(R, a)                                                           \
    asm volatile("ldmatrix.sync.aligned.m8n8.x4.trans.shared.b16 {%0,%1,%2,%3}, [%4];" \
        : "=r"((R)[0]), "=r"((R)[1]), "=r"((R)[2]), "=r"((R)[3]) : "r"(a))

__device__ __forceinline__ void mmab(float* c, const uint32_t* a,
                                     uint32_t b0, uint32_t b1) {
    asm volatile(
        "mma.sync.aligned.m16n8k16.row.col.f32.bf16.bf16.f32 "
        "{%0,%1,%2,%3}, {%4,%5,%6,%7}, {%8,%9}, {%0,%1,%2,%3};"
        : "+f"(c[0]), "+f"(c[1]), "+f"(c[2]), "+f"(c[3])
        : "r"(a[0]), "r"(a[1]), "r"(a[2]), "r"(a[3]), "r"(b0), "r"(b1));
}
// A fragment (16x16) for rows [row0,row0+16), k cols [k0,k0+16)
__device__ __forceinline__ void ldA(uint32_t R[4], uint32_t base, int row0,
                                    int k0, int lane) {
    LDSM4(R, base + swzo(row0 + (lane & 15), k0 + ((lane >> 4) << 3)));
}
// B fragments for 2 n8-tiles (n16), operand stored [n][k] (k contiguous)
__device__ __forceinline__ void ldB(uint32_t R[4], uint32_t base, int n0,
                                    int k0, int lane) {
    int g = lane >> 3;
    LDSM4(R, base + swzo(n0 + ((g >> 1) << 3) + (lane & 7), k0 + ((g & 1) << 3)));
}
// B fragments for 2 n8-tiles from operand stored [k][n] (row-major V)
__device__ __forceinline__ void ldVT(uint32_t R[4], uint32_t base, int k0,
                                     int n0, int lane) {
    int g = lane >> 3;
    LDSM4T(R, base + swzo(k0 + ((g & 1) << 3) + (lane & 7), n0 + ((g >> 1) << 3)));
}
// split fp32 pair -> packed bf16 hi pair + lo pair
__device__ __forceinline__ void split2(float v0, float v1,
                                       uint32_t& hp, uint32_t& lp) {
    __nv_bfloat16 h0 = __float2bfloat16(v0), h1 = __float2bfloat16(v1);
    float r0 = v0 - __bfloat162float(h0), r1 = v1 - __bfloat162float(h1);
    __nv_bfloat162 hh = __halves2bfloat162(h0, h1);
    __nv_bfloat162 ll = __halves2bfloat162(__float2bfloat16(r0),
                                           __float2bfloat16(r1));
    hp = *(uint32_t*)&hh;
    lp = *(uint32_t*)&ll;
}
// FFMA-only exp (MUFU on B300 is only 0.5/cyc/SM -> must avoid)
__device__ __forceinline__ float fexp(float x) {
    float y = fmaxf(x * 1.44269504f, -120.f);
    float n = rintf(y);
    float r = y - n;
    float p = 1.33335581e-3f;
    p = fmaf(p, r, 9.61812910e-3f);
    p = fmaf(p, r, 5.55041087e-2f);
    p = fmaf(p, r, 2.40226507e-1f);
    p = fmaf(p, r, 6.93147182e-1f);
    p = fmaf(p, r, 1.0f);
    return p * __int_as_float(((int)n + 127) << 23);
}
__device__ __forceinline__ float rmax2(float v) {
    v = fmaxf(v, __shfl_xor_sync(0xffffffffu, v, 1));
    v = fmaxf(v, __shfl_xor_sync(0xffffffffu, v, 2));
    return v;
}
__device__ __forceinline__ float rsum2(float v) {
    v += __shfl_xor_sync(0xffffffffu, v, 1);
    v += __shfl_xor_sync(0xffffffffu, v, 2);
    return v;
}

// ---------------------------------------------------------------------------
// Kernel 1: fp32 -> (hi, lo) bf16 split  (grid.y selects tensor)
// ---------------------------------------------------------------------------
__global__ void convert6(const float* __restrict__ q, const float* __restrict__ k,
                         const float* __restrict__ v, const float* __restrict__ wq,
                         const float* __restrict__ wk, const float* __restrict__ wv)
{
    const int which = blockIdx.y;
    const float* src;
    __nv_bfloat16 *dh, *dl;
    int n;
    switch (which) {
        case 0: src = q;  dh = g_inh[0]; dl = g_inl[0]; n = IN_ELEMS; break;
        case 1: src = k;  dh = g_inh[1]; dl = g_inl[1]; n = IN_ELEMS; break;
        case 2: src = v;  dh = g_inh[2]; dl = g_inl[2]; n = IN_ELEMS; break;
        case 3: src = wq; dh = g_Wh3[0]; dl = g_Wl3[0]; n = W_ELEMS;  break;
        case 4: src = wk; dh = g_Wh3[1]; dl = g_Wl3[1]; n = W_ELEMS;  break;
        default:src = wv; dh = g_Wh3[2]; dl = g_Wl3[2]; n = W_ELEMS;  break;
    }
    int i = (blockIdx.x * 256 + threadIdx.x) * 4;
    if (i >= n) return;
    float4 x = *(const float4*)(src + i);
    uint32_t h0, l0, h1, l1;
    split2(x.x, x.y, h0, l0);
    split2(x.z, x.w, h1, l1);
    *(uint2*)(dh + i) = make_uint2(h0, h1);
    *(uint2*)(dl + i) = make_uint2(l0, l1);
}

// ---------------------------------------------------------------------------
// Kernel 2: projection GEMM  C = A @ W^T + b  (bf16x3 HMMA)
// Block tile 128m x 64n, K-slab 64. 256 threads = 8 warps (2m x 4n of 64x16).
// grid: (8 n-blocks, 64 m-blocks, 3 z)
// ---------------------------------------------------------------------------
#define PJ_AH 0
#define PJ_AL 16384
#define PJ_WH 32768
#define PJ_WL 40960
#define PJ_SMEM 49152

__global__ __launch_bounds__(256)
void proj_mma(const float* __restrict__ bq, const float* __restrict__ bk,
              const float* __restrict__ bv)
{
    extern __shared__ char sm[];
    const uint32_t sb = smem_u32(sm);
    const int tid = threadIdx.x, lane = tid & 31, wid = tid >> 5;
    const int gid = lane >> 2, tig = lane & 3;
    const int wm = wid & 1, wn = wid >> 1;   // 2 x 4 warp grid
    const int z = blockIdx.z;
    const int n0g = blockIdx.x * 64, m0g = blockIdx.y * 128;

    const __nv_bfloat16 *Ah = g_inh[z], *Al = g_inl[z];
    const __nv_bfloat16 *Wh = g_Wh3[z], *Wl = g_Wl3[z];
    const float* bias = (z == 0) ? bq : (z == 1) ? bk : bv;
    __nv_bfloat16* Dh = (z == 0) ? g_Qh : (z == 1) ? g_Kh : g_Vh;
    __nv_bfloat16* Dl = (z == 0) ? g_Ql : (z == 1) ? g_Kl : g_Vl;

    float acc[4][2][4];
    #pragma unroll
    for (int mt = 0; mt < 4; mt++)
        #pragma unroll
        for (int nt = 0; nt < 2; nt++)
            #pragma unroll
            for (int i = 0; i < 4; i++) acc[mt][nt][i] = 0.f;

    for (int kk = 0; kk < D_MODEL; kk += 64) {
        __syncthreads();
        {
            const __nv_bfloat16* a0 = Ah + (size_t)m0g * 512 + kk;
            const __nv_bfloat16* a1 = Al + (size_t)m0g * 512 + kk;
            #pragma unroll
            for (int it = 0; it < 4; it++) {
                int idx = tid + it * 256;            // 0..1023
                int r = idx >> 3, c = (idx & 7) * 8;
                *(uint4*)(sm + PJ_AH + swzo(r, c)) = *(const uint4*)(a0 + r * 512 + c);
                *(uint4*)(sm + PJ_AL + swzo(r, c)) = *(const uint4*)(a1 + r * 512 + c);
            }
            const __nv_bfloat16* w0 = Wh + (size_t)n0g * 512 + kk;
            const __nv_bfloat16* w1 = Wl + (size_t)n0g * 512 + kk;
            #pragma unroll
            for (int it = 0; it < 2; it++) {
                int idx = tid + it * 256;            // 0..511
                int r = idx >> 3, c = (idx & 7) * 8;
                *(uint4*)(sm + PJ_WH + swzo(r, c)) = *(const uint4*)(w0 + r * 512 + c);
                *(uint4*)(sm + PJ_WL + swzo(r, c)) = *(const uint4*)(w1 + r * 512 + c);
            }
        }
        __syncthreads();

        #pragma unroll
        for (int ks = 0; ks < 4; ks++) {
            const int k0 = ks * 16;
            uint32_t ah[4][4], al[4][4], bh[4], bl[4];
            #pragma unroll
            for (int mt = 0; mt < 4; mt++) {
                ldA(ah[mt], sb + PJ_AH, wm * 64 + mt * 16, k0, lane);
                ldA(al[mt], sb + PJ_AL, wm * 64 + mt * 16, k0, lane);
            }
            ldB(bh, sb + PJ_WH, wn * 16, k0, lane);
            ldB(bl, sb + PJ_WL, wn * 16, k0, lane);
            #pragma unroll
            for (int mt = 0; mt < 4; mt++) {
                mmab(acc[mt][0], ah[mt], bh[0], bh[1]);
                mmab(acc[mt][1], ah[mt], bh[2], bh[3]);
                mmab(acc[mt][0], ah[mt], bl[0], bl[1]);
                mmab(acc[mt][1], ah[mt], bl[2], bl[3]);
                mmab(acc[mt][0], al[mt], bh[0], bh[1]);
                mmab(acc[mt][1], al[mt], bh[2], bh[3]);
            }
        }
    }

    // epilogue: +bias, split hi/lo, store head-major (one head per n-block)
    const int h = n0g >> 6;
    #pragma unroll
    for (int mt = 0; mt < 4; mt++) {
        #pragma unroll
        for (int nt = 0; nt < 2; nt++) {
            const int d = wn * 16 + nt * 8 + 2 * tig;
            const int n = n0g + d;
            const float b0 = bias[n], b1 = bias[n + 1];
            #pragma unroll
            for (int half = 0; half < 2; half++) {
                const int m = m0g + wm * 64 + mt * 16 + gid + half * 8;
                uint32_t hp, lp;
                split2(acc[mt][nt][half * 2] + b0, acc[mt][nt][half * 2 + 1] + b1,
                       hp, lp);
                const size_t o = ((size_t)h * M_TOTAL + m) * 64 + d;
                *(uint32_t*)(Dh + o) = hp;
                *(uint32_t*)(Dl + o) = lp;
            }
        }
    }
}

// ---------------------------------------------------------------------------
// Kernel 3: fused flash attention (bf16x3 HMMA, fast-exp online softmax)
// Block = 128 queries x 1 head. 8 warps, warp = m16 query stripe.
// grid: (16 q-tiles, 8 heads, 4 batch)
// ---------------------------------------------------------------------------
#define AT_QH 0
#define AT_QL 16384
#define AT_KH 32768
#define AT_KL 40960
#define AT_VH 49152
#define AT_VL 57344
#define AT_PH 65536
#define AT_PL 81920
#define AT_SMEM 98304

__global__ __launch_bounds__(256)
void attn_mma(float* __restrict__ out)
{
    extern __shared__ char sm[];
    const uint32_t sb = smem_u32(sm);
    const int tid = threadIdx.x, lane = tid & 31, wid = tid >> 5;
    const int gid = lane >> 2, tig = lane & 3;
    const int q0 = blockIdx.x * 128;
    const int h = blockIdx.y, b = blockIdx.z;

    const size_t qbase = ((size_t)h * M_TOTAL + (size_t)b * SEQ + q0) * 64;
    #pragma unroll
    for (int it = 0; it < 4; it++) {
        int idx = tid + it * 256;
        int r = idx >> 3, c = (idx & 7) * 8;
        *(uint4*)(sm + AT_QH + swzo(r, c)) = *(const uint4*)(g_Qh + qbase + r * 64 + c);
        *(uint4*)(sm + AT_QL + swzo(r, c)) = *(const uint4*)(g_Ql + qbase + r * 64 + c);
    }

    float o[8][4];
    #pragma unroll
    for (int nt = 0; nt < 8; nt++)
        #pragma unroll
        for (int i = 0; i < 4; i++) o[nt][i] = 0.f;
    float mrow0 = -1e30f, mrow1 = -1e30f, lrow0 = 0.f, lrow1 = 0.f;

    const size_t kvbase = ((size_t)h * M_TOTAL + (size_t)b * SEQ) * 64;

    for (int kt = 0; kt < SEQ / 64; kt++) {
        __syncthreads();
        {
            const size_t tb = kvbase + (size_t)kt * 64 * 64;
            #pragma unroll
            for (int it = 0; it < 2; it++) {
                int idx = tid + it * 256;            // 0..511
                int r = idx >> 3, c = (idx & 7) * 8;
                size_t src = tb + r * 64 + c;
                uint32_t dsw = swzo(r, c);
                *(uint4*)(sm + AT_KH + dsw) = *(const uint4*)(g_Kh + src);
                *(uint4*)(sm + AT_KL + dsw) = *(const uint4*)(g_Kl + src);
                *(uint4*)(sm + AT_VH + dsw) = *(const uint4*)(g_Vh + src);
                *(uint4*)(sm + AT_VL + dsw) = *(const uint4*)(g_Vl + src);
            }
        }
        __syncthreads();

        // ---- S = Q K^T (bf16x3) ----
        float s[8][4];
        #pragma unroll
        for (int nt = 0; nt < 8; nt++)
            #pragma unroll
            for (int i = 0; i < 4; i++) s[nt][i] = 0.f;

        #pragma unroll
        for (int ks = 0; ks < 4; ks++) {
            const int k0 = ks * 16;
            uint32_t qh[4], ql[4];
            ldA(qh, sb + AT_QH, wid * 16, k0, lane);
            ldA(ql, sb + AT_QL, wid * 16, k0, lane);
            #pragma unroll
            for (int np = 0; np < 4; np++) {
                uint32_t bh[4], bl[4];
                ldB(bh, sb + AT_KH, np * 16, k0, lane);
                ldB(bl, sb + AT_KL, np * 16, k0, lane);
                mmab(s[np * 2],     qh, bh[0], bh[1]);
                mmab(s[np * 2 + 1], qh, bh[2], bh[3]);
                mmab(s[np * 2],     qh, bl[0], bl[1]);
                mmab(s[np * 2 + 1], qh, bl[2], bl[3]);
                mmab(s[np * 2],     ql, bh[0], bh[1]);
                mmab(s[np * 2 + 1], ql, bh[2], bh[3]);
            }
        }

        // ---- online softmax (rows gid and gid+8 of this warp's stripe) ----
        float mx0 = -1e30f, mx1 = -1e30f;
        #pragma unroll
        for (int nt = 0; nt < 8; nt++) {
            #pragma unroll
            for (int i = 0; i < 4; i++) s[nt][i] *= 0.125f;
            mx0 = fmaxf(mx0, fmaxf(s[nt][0], s[nt][1]));
            mx1 = fmaxf(mx1, fmaxf(s[nt][2], s[nt][3]));
        }
        mx0 = rmax2(mx0);
        mx1 = rmax2(mx1);
        const float nm0 = fmaxf(mrow0, mx0), nm1 = fmaxf(mrow1, mx1);
        const float al0 = fexp(mrow0 - nm0), al1 = fexp(mrow1 - nm1);
        mrow0 = nm0; mrow1 = nm1;
        float sum0 = 0.f, sum1 = 0.f;
        #pragma unroll
        for (int nt = 0; nt < 8; nt++) {
            s[nt][0] = fexp(s[nt][0] - nm0);
            s[nt][1] = fexp(s[nt][1] - nm0);
            s[nt][2] = fexp(s[nt][2] - nm1);
            s[nt][3] = fexp(s[nt][3] - nm1);
            sum0 += s[nt][0] + s[nt][1];
            sum1 += s[nt][2] + s[nt][3];
        }
        lrow0 = lrow0 * al0 + rsum2(sum0);
        lrow1 = lrow1 * al1 + rsum2(sum1);
        #pragma unroll
        for (int nt = 0; nt < 8; nt++) {
            o[nt][0] *= al0; o[nt][1] *= al0;
            o[nt][2] *= al1; o[nt][3] *= al1;
        }

        // ---- stage P hi/lo in smem (own stripe only) ----
        {
            const int r0 = wid * 16 + gid;
            #pragma unroll
            for (int nt = 0; nt < 8; nt++) {
                const int col = nt * 8 + 2 * tig;
                uint32_t hp, lp;
                split2(s[nt][0], s[nt][1], hp, lp);
                uint32_t d0 = swzo(r0, col);
                *(uint32_t*)(sm + AT_PH + d0) = hp;
                *(uint32_t*)(sm + AT_PL + d0) = lp;
                split2(s[nt][2], s[nt][3], hp, lp);
                uint32_t d1 = swzo(r0 + 8, col);
                *(uint32_t*)(sm + AT_PH + d1) = hp;
                *(uint32_t*)(sm + AT_PL + d1) = lp;
            }
        }
        __syncwarp();

        // ---- O += P V (bf16x3) ----
        #pragma unroll
        for (int ks = 0; ks < 4; ks++) {
            const int k0 = ks * 16;
            uint32_t ph[4], pl[4];
            ldA(ph, sb + AT_PH, wid * 16, k0, lane);
            ldA(pl, sb + AT_PL, wid * 16, k0, lane);
            #pragma unroll
            for (int np = 0; np < 4; np++) {
                uint32_t vh[4], vl[4];
                ldVT(vh, sb + AT_VH, k0, np * 16, lane);
                ldVT(vl, sb + AT_VL, k0, np * 16, lane);
                mmab(o[np * 2],     ph, vh[0], vh[1]);
                mmab(o[np * 2 + 1], ph, vh[2], vh[3]);
                mmab(o[np * 2],     ph, vl[0], vl[1]);
                mmab(o[np * 2 + 1], ph, vl[2], vl[3]);
                mmab(o[np * 2],     pl, vh[0], vh[1]);
                mmab(o[np * 2 + 1], pl, vh[2], vh[3]);
            }
        }
    }

    // ---- normalize + store ----
    const float i0 = 1.f / lrow0, i1 = 1.f / lrow1;
    const int q = q0 + wid * 16 + gid;
    float* dst0 = out + ((size_t)b * SEQ + q) * D_MODEL + h * 64;
    float* dst1 = dst0 + (size_t)8 * D_MODEL;
    #pragma unroll
    for (int nt = 0; nt < 8; nt++) {
        const int col = nt * 8 + 2 * tig;
        *(float2*)(dst0 + col) = make_float2(o[nt][0] * i0, o[nt][1] * i0);
        *(float2*)(dst1 + col) = make_float2(o[nt][2] * i1, o[nt][3] * i1);
    }
}

// ---------------------------------------------------------------------------
// Launch
// ---------------------------------------------------------------------------
extern "C" void kernel_launch(void* const* d_in, const int* in_sizes, int n_in,
                              void* d_out, int out_size)
{
    const float* q  = (const float*)d_in[0];
    const float* k  = (const float*)d_in[1];
    const float* v  = (const float*)d_in[2];
    const float* Wq = (const float*)d_in[3];
    const float* bq = (const float*)d_in[4];
    const float* Wk = (const float*)d_in[5];
    const float* bk = (const float*)d_in[6];
    const float* Wv = (const float*)d_in[7];
    const float* bv = (const float*)d_in[8];
    float* out = (float*)d_out;

    cudaFuncSetAttribute(proj_mma, cudaFuncAttributeMaxDynamicSharedMemorySize,
                         PJ_SMEM);
    cudaFuncSetAttribute(attn_mma, cudaFuncAttributeMaxDynamicSharedMemorySize,
                         AT_SMEM);

    dim3 gcv(IN_ELEMS / (256 * 4), 6);
    convert6<<<gcv, 256>>>(q, k, v, Wq, Wk, Wv);

    dim3 gproj(D_MODEL / 64, M_TOTAL / 128, 3);
    proj_mma<<<gproj, 256, PJ_SMEM>>>(bq, bk, bv);

    dim3 gattn(SEQ / 128, NUM_HEADS, BATCH);
    attn_mma<<<gattn, 256, AT_SMEM>>>(out);
}

// round 6
// speedup vs baseline: 4.3208x; 2.0177x over previous
#include <cuda_runtime.h>
#include <cuda_fp16.h>
#include <cstdint>

#define D_MODEL   512
#define NUM_HEADS 8
#define HEAD_DIM  64
#define SEQ       2048
#define BATCH     4
#define M_TOTAL   (BATCH * SEQ)          // 8192
#define IN_ELEMS  (M_TOTAL * D_MODEL)    // 4194304
#define W_ELEMS   (D_MODEL * D_MODEL)

// ---------------------------------------------------------------------------
// Scratch
// ---------------------------------------------------------------------------
__device__ __half g_inh[3][IN_ELEMS];
__device__ __half g_Wh3[3][W_ELEMS];
// projected, head-major: idx = (h*M_TOTAL + m)*64 + d    (Q pre-scaled by 1/8)
__device__ __half g_Qh[IN_ELEMS], g_Kh[IN_ELEMS], g_Vh[IN_ELEMS];

// ---------------------------------------------------------------------------
// Helpers
// ---------------------------------------------------------------------------
__device__ __forceinline__ uint32_t smem_u32(const void* p) {
    uint32_t a;
    asm("{ .reg .u64 t; cvta.to.shared.u64 t, %1; cvt.u32.u64 %0, t; }"
        : "=r"(a) : "l"(p));
    return a;
}
// swizzled byte offset; tiles have 64-half (128B) rows
__device__ __forceinline__ uint32_t swzo(int row, int col) {
    uint32_t bo = (uint32_t)row * 128u + (uint32_t)col * 2u;
    return bo ^ ((bo >> 3) & 0x70u);
}
#define LDSM4(R, a)                                                            \
    asm volatile("ldmatrix.sync.aligned.m8n8.x4.shared.b16 {%0,%1,%2,%3}, [%4];" \
        : "=r"((R)[0]), "=r"((R)[1]), "=r"((R)[2]), "=r"((R)[3]) : "r"(a))
#define LDSM4T(R, a)                                                           \
    asm volatile("ldmatrix.sync.aligned.m8n8.x4.trans.shared.b16 {%0,%1,%2,%3}, [%4];" \
        : "=r"((R)[0]), "=r"((R)[1]), "=r"((R)[2]), "=r"((R)[3]) : "r"(a))

#define CP16(dst, src)                                                         \
    asm volatile("cp.async.cg.shared.global [%0], [%1], 16;"                    \
                 :: "r"(dst), "l"(src) : "memory")
#define CP_COMMIT() asm volatile("cp.async.commit_group;" ::: "memory")
#define CP_WAIT(n)  asm volatile("cp.async.wait_group %0;" :: "n"(n) : "memory")

__device__ __forceinline__ void mmah(float* c, const uint32_t* a,
                                     uint32_t b0, uint32_t b1) {
    asm volatile(
        "mma.sync.aligned.m16n8k16.row.col.f32.f16.f16.f32 "
        "{%0,%1,%2,%3}, {%4,%5,%6,%7}, {%8,%9}, {%0,%1,%2,%3};"
        : "+f"(c[0]), "+f"(c[1]), "+f"(c[2]), "+f"(c[3])
        : "r"(a[0]), "r"(a[1]), "r"(a[2]), "r"(a[3]), "r"(b0), "r"(b1));
}
__device__ __forceinline__ void ldA(uint32_t R[4], uint32_t base, int row0,
                                    int k0, int lane) {
    LDSM4(R, base + swzo(row0 + (lane & 15), k0 + ((lane >> 4) << 3)));
}
// B (2 n8-tiles) from operand stored [n][k]
__device__ __forceinline__ void ldB(uint32_t R[4], uint32_t base, int n0,
                                    int k0, int lane) {
    int g = lane >> 3;
    LDSM4(R, base + swzo(n0 + ((g >> 1) << 3) + (lane & 7), k0 + ((g & 1) << 3)));
}
// B (2 n8-tiles) from operand stored [k][n] (natural V)
__device__ __forceinline__ void ldVT(uint32_t R[4], uint32_t base, int k0,
                                     int n0, int lane) {
    int g = lane >> 3;
    LDSM4T(R, base + swzo(k0 + ((g & 1) << 3) + (lane & 7), n0 + ((g >> 1) << 3)));
}
// FFMA-only exp (MUFU on B300 is 0.5/cyc/SM -> avoid)
__device__ __forceinline__ float fexp(float x) {
    float y = fmaxf(x * 1.44269504f, -120.f);
    float n = rintf(y);
    float r = y - n;
    float p = 1.33335581e-3f;
    p = fmaf(p, r, 9.61812910e-3f);
    p = fmaf(p, r, 5.55041087e-2f);
    p = fmaf(p, r, 2.40226507e-1f);
    p = fmaf(p, r, 6.93147182e-1f);
    p = fmaf(p, r, 1.0f);
    return p * __int_as_float(((int)n + 127) << 23);
}
__device__ __forceinline__ float rmax2(float v) {
    v = fmaxf(v, __shfl_xor_sync(0xffffffffu, v, 1));
    v = fmaxf(v, __shfl_xor_sync(0xffffffffu, v, 2));
    return v;
}
__device__ __forceinline__ float rsum2(float v) {
    v += __shfl_xor_sync(0xffffffffu, v, 1);
    v += __shfl_xor_sync(0xffffffffu, v, 2);
    return v;
}

// ---------------------------------------------------------------------------
// Kernel 1: fp32 -> fp16
// ---------------------------------------------------------------------------
__global__ void convert6(const float* __restrict__ q, const float* __restrict__ k,
                         const float* __restrict__ v, const float* __restrict__ wq,
                         const float* __restrict__ wk, const float* __restrict__ wv)
{
    const int which = blockIdx.y;
    const float* src;
    __half* dh;
    int n;
    switch (which) {
        case 0: src = q;  dh = g_inh[0]; n = IN_ELEMS; break;
        case 1: src = k;  dh = g_inh[1]; n = IN_ELEMS; break;
        case 2: src = v;  dh = g_inh[2]; n = IN_ELEMS; break;
        case 3: src = wq; dh = g_Wh3[0]; n = W_ELEMS;  break;
        case 4: src = wk; dh = g_Wh3[1]; n = W_ELEMS;  break;
        default:src = wv; dh = g_Wh3[2]; n = W_ELEMS;  break;
    }
    int i = (blockIdx.x * 256 + threadIdx.x) * 4;
    if (i >= n) return;
    float4 x = *(const float4*)(src + i);
    __half2 a = __floats2half2_rn(x.x, x.y);
    __half2 b = __floats2half2_rn(x.z, x.w);
    *(uint2*)(dh + i) = make_uint2(*(uint32_t*)&a, *(uint32_t*)&b);
}

// ---------------------------------------------------------------------------
// Kernel 2: projection GEMM  C = A @ W^T + b (fp16 HMMA)
// Block tile 128m x 128n, K-slab 64. 8 warps (2m x 4n, warp = 64x32).
// grid: (4, 64, 3)
// ---------------------------------------------------------------------------
#define PJ_A0 0
#define PJ_W0 16384
#define PJ_SMEM 32768

__global__ __launch_bounds__(256)
void proj_mma(const float* __restrict__ bq, const float* __restrict__ bk,
              const float* __restrict__ bv)
{
    extern __shared__ char sm[];
    const uint32_t sb = smem_u32(sm);
    const int tid = threadIdx.x, lane = tid & 31, wid = tid >> 5;
    const int gid = lane >> 2, tig = lane & 3;
    const int wm = wid & 1, wn = wid >> 1;
    const int z = blockIdx.z;
    const int n0g = blockIdx.x * 128, m0g = blockIdx.y * 128;

    const __half* A = g_inh[z];
    const __half* W = g_Wh3[z];
    const float* bias = (z == 0) ? bq : (z == 1) ? bk : bv;
    __half* D = (z == 0) ? g_Qh : (z == 1) ? g_Kh : g_Vh;

    float acc[4][4][4];
    #pragma unroll
    for (int mt = 0; mt < 4; mt++)
        #pragma unroll
        for (int nt = 0; nt < 4; nt++)
            #pragma unroll
            for (int i = 0; i < 4; i++) acc[mt][nt][i] = 0.f;

    for (int kk = 0; kk < D_MODEL; kk += 64) {
        __syncthreads();
        #pragma unroll
        for (int it = 0; it < 4; it++) {
            int idx = tid + it * 256;            // 0..1023
            int r = idx >> 3, c = (idx & 7) * 8;
            *(uint4*)(sm + PJ_A0 + swzo(r, c)) =
                *(const uint4*)(A + (size_t)(m0g + r) * 512 + kk + c);
            *(uint4*)(sm + PJ_W0 + swzo(r, c)) =
                *(const uint4*)(W + (size_t)(n0g + r) * 512 + kk + c);
        }
        __syncthreads();

        #pragma unroll
        for (int ks = 0; ks < 4; ks++) {
            const int k0 = ks * 16;
            uint32_t a[4][4], b[2][4];
            #pragma unroll
            for (int mt = 0; mt < 4; mt++)
                ldA(a[mt], sb + PJ_A0, wm * 64 + mt * 16, k0, lane);
            #pragma unroll
            for (int np = 0; np < 2; np++)
                ldB(b[np], sb + PJ_W0, wn * 32 + np * 16, k0, lane);
            #pragma unroll
            for (int mt = 0; mt < 4; mt++)
                #pragma unroll
                for (int np = 0; np < 2; np++) {
                    mmah(acc[mt][np * 2],     a[mt], b[np][0], b[np][1]);
                    mmah(acc[mt][np * 2 + 1], a[mt], b[np][2], b[np][3]);
                }
        }
    }

    // epilogue: +bias, (Q also * 1/8), store head-major fp16
    const float sc = (z == 0) ? 0.125f : 1.f;
    #pragma unroll
    for (int mt = 0; mt < 4; mt++) {
        #pragma unroll
        for (int nt = 0; nt < 4; nt++) {
            const int n = n0g + wn * 32 + nt * 8 + 2 * tig;
            const int h = n >> 6, d = n & 63;
            const float b0 = bias[n], b1 = bias[n + 1];
            #pragma unroll
            for (int half = 0; half < 2; half++) {
                const int m = m0g + wm * 64 + mt * 16 + gid + half * 8;
                __half2 hv = __floats2half2_rn(
                    (acc[mt][nt][half * 2]     + b0) * sc,
                    (acc[mt][nt][half * 2 + 1] + b1) * sc);
                *(uint32_t*)(D + ((size_t)h * M_TOTAL + m) * 64 + d) =
                    *(uint32_t*)&hv;
            }
        }
    }
}

// ---------------------------------------------------------------------------
// Kernel 3: fused flash attention (fp16 HMMA, cp.async double-buffered K/V)
// Block = 128 queries x 1 head, 8 warps (warp = 16-query stripe).
// grid: (16, 8, 4)
// ---------------------------------------------------------------------------
#define AT_Q  0
#define AT_K0 16384
#define AT_V0 24576
#define AT_K1 32768
#define AT_V1 40960
#define AT_P  49152
#define AT_SMEM 65536

__device__ __forceinline__ void issue_kv(uint32_t sb, int buf,
                                         const __half* Kp, const __half* Vp,
                                         int tid) {
    const uint32_t kof = sb + AT_K0 + buf * 16384;
    const uint32_t vof = sb + AT_V0 + buf * 16384;
    #pragma unroll
    for (int it = 0; it < 2; it++) {
        int idx = tid + it * 256;                // 0..511
        int r = idx >> 3, c = (idx & 7) * 8;
        uint32_t sw = swzo(r, c);
        CP16(kof + sw, Kp + r * 64 + c);
        CP16(vof + sw, Vp + r * 64 + c);
    }
}

__global__ __launch_bounds__(256)
void attn_mma(float* __restrict__ out)
{
    extern __shared__ char sm[];
    const uint32_t sb = smem_u32(sm);
    const int tid = threadIdx.x, lane = tid & 31, wid = tid >> 5;
    const int gid = lane >> 2, tig = lane & 3;
    const int q0 = blockIdx.x * 128;
    const int h = blockIdx.y, b = blockIdx.z;

    const size_t qbase  = ((size_t)h * M_TOTAL + (size_t)b * SEQ + q0) * 64;
    const size_t kvbase = ((size_t)h * M_TOTAL + (size_t)b * SEQ) * 64;
    const __half* Kb = g_Kh + kvbase;
    const __half* Vb = g_Vh + kvbase;

    // prologue: start tile 0 loads, then stage Q
    issue_kv(sb, 0, Kb, Vb, tid);
    CP_COMMIT();
    #pragma unroll
    for (int it = 0; it < 4; it++) {
        int idx = tid + it * 256;
        int r = idx >> 3, c = (idx & 7) * 8;
        *(uint4*)(sm + AT_Q + swzo(r, c)) =
            *(const uint4*)(g_Qh + qbase + r * 64 + c);
    }

    float o[8][4];
    #pragma unroll
    for (int nt = 0; nt < 8; nt++)
        #pragma unroll
        for (int i = 0; i < 4; i++) o[nt][i] = 0.f;
    float mrow0 = -1e30f, mrow1 = -1e30f, lrow0 = 0.f, lrow1 = 0.f;

    for (int kt = 0; kt < SEQ / 64; kt++) {
        const uint32_t kof = AT_K0 + (kt & 1) * 16384;
        const uint32_t vof = AT_V0 + (kt & 1) * 16384;
        if (kt < SEQ / 64 - 1) {
            issue_kv(sb, (kt + 1) & 1, Kb + (kt + 1) * 4096,
                     Vb + (kt + 1) * 4096, tid);
            CP_COMMIT();
            CP_WAIT(1);
        } else {
            CP_WAIT(0);
        }
        __syncthreads();

        // ---- S = Q K^T ----
        float s[8][4];
        #pragma unroll
        for (int nt = 0; nt < 8; nt++)
            #pragma unroll
            for (int i = 0; i < 4; i++) s[nt][i] = 0.f;

        #pragma unroll
        for (int ks = 0; ks < 4; ks++) {
            const int k0 = ks * 16;
            uint32_t qf[4];
            ldA(qf, sb + AT_Q, wid * 16, k0, lane);
            #pragma unroll
            for (int np = 0; np < 4; np++) {
                uint32_t bf[4];
                ldB(bf, sb + kof, np * 16, k0, lane);
                mmah(s[np * 2],     qf, bf[0], bf[1]);
                mmah(s[np * 2 + 1], qf, bf[2], bf[3]);
            }
        }

        // ---- online softmax (scale already folded into Q) ----
        float mx0 = -1e30f, mx1 = -1e30f;
        #pragma unroll
        for (int nt = 0; nt < 8; nt++) {
            mx0 = fmaxf(mx0, fmaxf(s[nt][0], s[nt][1]));
            mx1 = fmaxf(mx1, fmaxf(s[nt][2], s[nt][3]));
        }
        mx0 = rmax2(mx0);
        mx1 = rmax2(mx1);
        const float nm0 = fmaxf(mrow0, mx0), nm1 = fmaxf(mrow1, mx1);
        const float al0 = fexp(mrow0 - nm0), al1 = fexp(mrow1 - nm1);
        mrow0 = nm0; mrow1 = nm1;
        float sum0 = 0.f, sum1 = 0.f;
        #pragma unroll
        for (int nt = 0; nt < 8; nt++) {
            s[nt][0] = fexp(s[nt][0] - nm0);
            s[nt][1] = fexp(s[nt][1] - nm0);
            s[nt][2] = fexp(s[nt][2] - nm1);
            s[nt][3] = fexp(s[nt][3] - nm1);
            sum0 += s[nt][0] + s[nt][1];
            sum1 += s[nt][2] + s[nt][3];
        }
        lrow0 = lrow0 * al0 + rsum2(sum0);
        lrow1 = lrow1 * al1 + rsum2(sum1);
        #pragma unroll
        for (int nt = 0; nt < 8; nt++) {
            o[nt][0] *= al0; o[nt][1] *= al0;
            o[nt][2] *= al1; o[nt][3] *= al1;
        }

        // ---- stage P (own 16-row stripe; warp-local) ----
        {
            const int r0 = wid * 16 + gid;
            #pragma unroll
            for (int nt = 0; nt < 8; nt++) {
                const int col = nt * 8 + 2 * tig;
                __half2 p0 = __floats2half2_rn(s[nt][0], s[nt][1]);
                __half2 p1 = __floats2half2_rn(s[nt][2], s[nt][3]);
                *(uint32_t*)(sm + AT_P + swzo(r0, col))     = *(uint32_t*)&p0;
                *(uint32_t*)(sm + AT_P + swzo(r0 + 8, col)) = *(uint32_t*)&p1;
            }
        }
        __syncwarp();

        // ---- O += P V ----
        #pragma unroll
        for (int ks = 0; ks < 4; ks++) {
            const int k0 = ks * 16;
            uint32_t pf[4];
            ldA(pf, sb + AT_P, wid * 16, k0, lane);
            #pragma unroll
            for (int np = 0; np < 4; np++) {
                uint32_t vf[4];
                ldVT(vf, sb + vof, k0, np * 16, lane);
                mmah(o[np * 2],     pf, vf[0], vf[1]);
                mmah(o[np * 2 + 1], pf, vf[2], vf[3]);
            }
        }
        __syncthreads();   // all warps done with this K/V buffer
    }

    // ---- normalize + store ----
    const float i0 = 1.f / lrow0, i1 = 1.f / lrow1;
    const int q = q0 + wid * 16 + gid;
    float* dst0 = out + ((size_t)b * SEQ + q) * D_MODEL + h * 64;
    float* dst1 = dst0 + (size_t)8 * D_MODEL;
    #pragma unroll
    for (int nt = 0; nt < 8; nt++) {
        const int col = nt * 8 + 2 * tig;
        *(float2*)(dst0 + col) = make_float2(o[nt][0] * i0, o[nt][1] * i0);
        *(float2*)(dst1 + col) = make_float2(o[nt][2] * i1, o[nt][3] * i1);
    }
}

// ---------------------------------------------------------------------------
// Launch
// ---------------------------------------------------------------------------
extern "C" void kernel_launch(void* const* d_in, const int* in_sizes, int n_in,
                              void* d_out, int out_size)
{
    const float* q  = (const float*)d_in[0];
    const float* k  = (const float*)d_in[1];
    const float* v  = (const float*)d_in[2];
    const float* Wq = (const float*)d_in[3];
    const float* bq = (const float*)d_in[4];
    const float* Wk = (const float*)d_in[5];
    const float* bk = (const float*)d_in[6];
    const float* Wv = (const float*)d_in[7];
    const float* bv = (const float*)d_in[8];
    float* out = (float*)d_out;

    cudaFuncSetAttribute(proj_mma, cudaFuncAttributeMaxDynamicSharedMemorySize,
                         PJ_SMEM);
    cudaFuncSetAttribute(attn_mma, cudaFuncAttributeMaxDynamicSharedMemorySize,
                         AT_SMEM);

    dim3 gcv(IN_ELEMS / (256 * 4), 6);
    convert6<<<gcv, 256>>>(q, k, v, Wq, Wk, Wv);

    dim3 gproj(D_MODEL / 128, M_TOTAL / 128, 3);
    proj_mma<<<gproj, 256, PJ_SMEM>>>(bq, bk, bv);

    dim3 gattn(SEQ / 128, NUM_HEADS, BATCH);
    attn_mma<<<gattn, 256, AT_SMEM>>>(out);
}

// round 7
// speedup vs baseline: 7.0701x; 1.6363x over previous
#include <cuda_runtime.h>
#include <cuda_fp16.h>
#include <cstdint>

#define D_MODEL   512
#define NUM_HEADS 8
#define HEAD_DIM  64
#define SEQ       2048
#define BATCH     4
#define M_TOTAL   (BATCH * SEQ)          // 8192
#define IN_ELEMS  (M_TOTAL * D_MODEL)    // 4194304
#define W_ELEMS   (D_MODEL * D_MODEL)

// Q pre-scale: (1/sqrt(64)) * log2(e)  -> scores come out in log2 domain
#define QSCALE 0.1803368801111244f

// ---------------------------------------------------------------------------
// Scratch
// ---------------------------------------------------------------------------
__device__ __half g_inh[3][IN_ELEMS];
__device__ __half g_Wh3[3][W_ELEMS];
// projected, head-major: idx = (h*M_TOTAL + m)*64 + d
__device__ __half g_Qh[IN_ELEMS], g_Kh[IN_ELEMS], g_Vh[IN_ELEMS];

// ---------------------------------------------------------------------------
// Helpers
// ---------------------------------------------------------------------------
__device__ __forceinline__ uint32_t smem_u32(const void* p) {
    uint32_t a;
    asm("{ .reg .u64 t; cvta.to.shared.u64 t, %1; cvt.u32.u64 %0, t; }"
        : "=r"(a) : "l"(p));
    return a;
}
__device__ __forceinline__ uint32_t swzo(int row, int col) {
    uint32_t bo = (uint32_t)row * 128u + (uint32_t)col * 2u;
    return bo ^ ((bo >> 3) & 0x70u);
}
#define LDSM4(R, a)                                                            \
    asm volatile("ldmatrix.sync.aligned.m8n8.x4.shared.b16 {%0,%1,%2,%3}, [%4];" \
        : "=r"((R)[0]), "=r"((R)[1]), "=r"((R)[2]), "=r"((R)[3]) : "r"(a))
#define LDSM4T(R, a)                                                           \
    asm volatile("ldmatrix.sync.aligned.m8n8.x4.trans.shared.b16 {%0,%1,%2,%3}, [%4];" \
        : "=r"((R)[0]), "=r"((R)[1]), "=r"((R)[2]), "=r"((R)[3]) : "r"(a))
#define CP16(dst, src)                                                         \
    asm volatile("cp.async.cg.shared.global [%0], [%1], 16;"                    \
                 :: "r"(dst), "l"(src) : "memory")
#define CP_COMMIT() asm volatile("cp.async.commit_group;" ::: "memory")
#define CP_WAIT(n)  asm volatile("cp.async.wait_group %0;" :: "n"(n) : "memory")

__device__ __forceinline__ void mmah(float* c, const uint32_t* a,
                                     uint32_t b0, uint32_t b1) {
    asm volatile(
        "mma.sync.aligned.m16n8k16.row.col.f32.f16.f16.f32 "
        "{%0,%1,%2,%3}, {%4,%5,%6,%7}, {%8,%9}, {%0,%1,%2,%3};"
        : "+f"(c[0]), "+f"(c[1]), "+f"(c[2]), "+f"(c[3])
        : "r"(a[0]), "r"(a[1]), "r"(a[2]), "r"(a[3]), "r"(b0), "r"(b1));
}
__device__ __forceinline__ void ldA(uint32_t R[4], uint32_t base, int row0,
                                    int k0, int lane) {
    LDSM4(R, base + swzo(row0 + (lane & 15), k0 + ((lane >> 4) << 3)));
}
__device__ __forceinline__ void ldB(uint32_t R[4], uint32_t base, int n0,
                                    int k0, int lane) {
    int g = lane >> 3;
    LDSM4(R, base + swzo(n0 + ((g >> 1) << 3) + (lane & 7), k0 + ((g & 1) << 3)));
}
__device__ __forceinline__ void ldVT(uint32_t R[4], uint32_t base, int k0,
                                     int n0, int lane) {
    int g = lane >> 3;
    LDSM4T(R, base + swzo(k0 + ((g & 1) << 3) + (lane & 7), n0 + ((g >> 1) << 3)));
}
// single-MUFU exp2 (16 elem/cyc/SM; offloads the fma pipe)
__device__ __forceinline__ float ex2(float x) {
    float r;
    asm("ex2.approx.f32 %0, %1;" : "=f"(r) : "f"(x));
    return r;
}
__device__ __forceinline__ uint32_t packh2(float a, float b) {
    __half2 h = __floats2half2_rn(a, b);
    return *(uint32_t*)&h;
}
__device__ __forceinline__ float rmax2(float v) {
    v = fmaxf(v, __shfl_xor_sync(0xffffffffu, v, 1));
    v = fmaxf(v, __shfl_xor_sync(0xffffffffu, v, 2));
    return v;
}
__device__ __forceinline__ float rsum2(float v) {
    v += __shfl_xor_sync(0xffffffffu, v, 1);
    v += __shfl_xor_sync(0xffffffffu, v, 2);
    return v;
}

// ---------------------------------------------------------------------------
// Kernel 1: fp32 -> fp16
// ---------------------------------------------------------------------------
__global__ void convert6(const float* __restrict__ q, const float* __restrict__ k,
                         const float* __restrict__ v, const float* __restrict__ wq,
                         const float* __restrict__ wk, const float* __restrict__ wv)
{
    const int which = blockIdx.y;
    const float* src;
    __half* dh;
    int n;
    switch (which) {
        case 0: src = q;  dh = g_inh[0]; n = IN_ELEMS; break;
        case 1: src = k;  dh = g_inh[1]; n = IN_ELEMS; break;
        case 2: src = v;  dh = g_inh[2]; n = IN_ELEMS; break;
        case 3: src = wq; dh = g_Wh3[0]; n = W_ELEMS;  break;
        case 4: src = wk; dh = g_Wh3[1]; n = W_ELEMS;  break;
        default:src = wv; dh = g_Wh3[2]; n = W_ELEMS;  break;
    }
    int i = (blockIdx.x * 256 + threadIdx.x) * 4;
    if (i >= n) return;
    float4 x = *(const float4*)(src + i);
    __half2 a = __floats2half2_rn(x.x, x.y);
    __half2 b = __floats2half2_rn(x.z, x.w);
    *(uint2*)(dh + i) = make_uint2(*(uint32_t*)&a, *(uint32_t*)&b);
}

// ---------------------------------------------------------------------------
// Kernel 2: projection GEMM  C = A @ W^T + b (fp16 HMMA, cp.async 2-stage)
// Block tile 128m x 128n, K-slab 64. 8 warps (2m x 4n). grid: (4, 64, 3)
// ---------------------------------------------------------------------------
#define PJ_A0 0
#define PJ_W0 16384
#define PJ_A1 32768
#define PJ_W1 49152
#define PJ_SMEM 65536

__device__ __forceinline__ void pj_issue(uint32_t sb, int buf,
                                         const __half* A, const __half* W,
                                         int m0g, int n0g, int kk, int tid) {
    const uint32_t aof = sb + (buf ? PJ_A1 : PJ_A0);
    const uint32_t wof = sb + (buf ? PJ_W1 : PJ_W0);
    #pragma unroll
    for (int it = 0; it < 4; it++) {
        int idx = tid + it * 256;            // 0..1023
        int r = idx >> 3, c = (idx & 7) * 8;
        uint32_t sw = swzo(r, c);
        CP16(aof + sw, A + (size_t)(m0g + r) * 512 + kk + c);
        CP16(wof + sw, W + (size_t)(n0g + r) * 512 + kk + c);
    }
}

__global__ __launch_bounds__(256)
void proj_mma(const float* __restrict__ bq, const float* __restrict__ bk,
              const float* __restrict__ bv)
{
    extern __shared__ char sm[];
    const uint32_t sb = smem_u32(sm);
    const int tid = threadIdx.x, lane = tid & 31, wid = tid >> 5;
    const int gid = lane >> 2, tig = lane & 3;
    const int wm = wid & 1, wn = wid >> 1;
    const int z = blockIdx.z;
    const int n0g = blockIdx.x * 128, m0g = blockIdx.y * 128;

    const __half* A = g_inh[z];
    const __half* W = g_Wh3[z];
    const float* bias = (z == 0) ? bq : (z == 1) ? bk : bv;
    __half* D = (z == 0) ? g_Qh : (z == 1) ? g_Kh : g_Vh;

    float acc[4][4][4];
    #pragma unroll
    for (int mt = 0; mt < 4; mt++)
        #pragma unroll
        for (int nt = 0; nt < 4; nt++)
            #pragma unroll
            for (int i = 0; i < 4; i++) acc[mt][nt][i] = 0.f;

    pj_issue(sb, 0, A, W, m0g, n0g, 0, tid);
    CP_COMMIT();

    for (int ks8 = 0; ks8 < 8; ks8++) {
        CP_WAIT(0);
        __syncthreads();
        if (ks8 + 1 < 8) {
            pj_issue(sb, (ks8 + 1) & 1, A, W, m0g, n0g, (ks8 + 1) * 64, tid);
            CP_COMMIT();
        }
        const uint32_t aof = sb + ((ks8 & 1) ? PJ_A1 : PJ_A0);
        const uint32_t wof = sb + ((ks8 & 1) ? PJ_W1 : PJ_W0);
        #pragma unroll
        for (int ks = 0; ks < 4; ks++) {
            const int k0 = ks * 16;
            uint32_t a[4][4], b[2][4];
            #pragma unroll
            for (int mt = 0; mt < 4; mt++)
                ldA(a[mt], aof, wm * 64 + mt * 16, k0, lane);
            #pragma unroll
            for (int np = 0; np < 2; np++)
                ldB(b[np], wof, wn * 32 + np * 16, k0, lane);
            #pragma unroll
            for (int mt = 0; mt < 4; mt++)
                #pragma unroll
                for (int np = 0; np < 2; np++) {
                    mmah(acc[mt][np * 2],     a[mt], b[np][0], b[np][1]);
                    mmah(acc[mt][np * 2 + 1], a[mt], b[np][2], b[np][3]);
                }
        }
    }

    // epilogue: +bias (Q also * QSCALE), store head-major fp16
    const float sc = (z == 0) ? QSCALE : 1.f;
    #pragma unroll
    for (int mt = 0; mt < 4; mt++) {
        #pragma unroll
        for (int nt = 0; nt < 4; nt++) {
            const int n = n0g + wn * 32 + nt * 8 + 2 * tig;
            const int h = n >> 6, d = n & 63;
            const float b0 = bias[n], b1 = bias[n + 1];
            #pragma unroll
            for (int half = 0; half < 2; half++) {
                const int m = m0g + wm * 64 + mt * 16 + gid + half * 8;
                __half2 hv = __floats2half2_rn(
                    (acc[mt][nt][half * 2]     + b0) * sc,
                    (acc[mt][nt][half * 2 + 1] + b1) * sc);
                *(uint32_t*)(D + ((size_t)h * M_TOTAL + m) * 64 + d) =
                    *(uint32_t*)&hv;
            }
        }
    }
}

// ---------------------------------------------------------------------------
// Kernel 3: fused flash attention
// fp16 HMMA, P kept in registers (FA2 fragment reuse), ex2-softmax,
// cp.async 2-stage single-sync pipeline. Block = 128 queries x 1 head.
// grid: (16, 8, 4)
// ---------------------------------------------------------------------------
#define AT_Q  0
#define AT_K0 16384
#define AT_V0 24576
#define AT_K1 32768
#define AT_V1 40960
#define AT_SMEM 49152
#define NTILES (SEQ / 64)

__device__ __forceinline__ void issue_kv(uint32_t sb, int buf,
                                         const __half* Kp, const __half* Vp,
                                         int tid) {
    const uint32_t kof = sb + AT_K0 + buf * 16384;
    const uint32_t vof = sb + AT_V0 + buf * 16384;
    #pragma unroll
    for (int it = 0; it < 2; it++) {
        int idx = tid + it * 256;                // 0..511
        int r = idx >> 3, c = (idx & 7) * 8;
        uint32_t sw = swzo(r, c);
        CP16(kof + sw, Kp + r * 64 + c);
        CP16(vof + sw, Vp + r * 64 + c);
    }
}

__global__ __launch_bounds__(256)
void attn_mma(float* __restrict__ out)
{
    extern __shared__ char sm[];
    const uint32_t sb = smem_u32(sm);
    const int tid = threadIdx.x, lane = tid & 31, wid = tid >> 5;
    const int gid = lane >> 2, tig = lane & 3;
    const int q0 = blockIdx.x * 128;
    const int h = blockIdx.y, b = blockIdx.z;

    const size_t qbase  = ((size_t)h * M_TOTAL + (size_t)b * SEQ + q0) * 64;
    const size_t kvbase = ((size_t)h * M_TOTAL + (size_t)b * SEQ) * 64;
    const __half* Kb = g_Kh + kvbase;
    const __half* Vb = g_Vh + kvbase;

    issue_kv(sb, 0, Kb, Vb, tid);
    CP_COMMIT();
    #pragma unroll
    for (int it = 0; it < 4; it++) {
        int idx = tid + it * 256;
        int r = idx >> 3, c = (idx & 7) * 8;
        *(uint4*)(sm + AT_Q + swzo(r, c)) =
            *(const uint4*)(g_Qh + qbase + r * 64 + c);
    }

    float o[8][4];
    #pragma unroll
    for (int nt = 0; nt < 8; nt++)
        #pragma unroll
        for (int i = 0; i < 4; i++) o[nt][i] = 0.f;
    float mrow0 = -1e30f, mrow1 = -1e30f, lrow0 = 0.f, lrow1 = 0.f;

    for (int kt = 0; kt < NTILES; kt++) {
        CP_WAIT(0);
        __syncthreads();          // data visible; nobody re-reads other buffer
        if (kt + 1 < NTILES) {
            issue_kv(sb, (kt + 1) & 1, Kb + (kt + 1) * 4096,
                     Vb + (kt + 1) * 4096, tid);
            CP_COMMIT();
        }
        const uint32_t kof = sb + AT_K0 + (kt & 1) * 16384;
        const uint32_t vof = sb + AT_V0 + (kt & 1) * 16384;

        // ---- S = Q K^T (scores already in log2 domain via QSCALE) ----
        float s[8][4];
        #pragma unroll
        for (int nt = 0; nt < 8; nt++)
            #pragma unroll
            for (int i = 0; i < 4; i++) s[nt][i] = 0.f;

        #pragma unroll
        for (int ks = 0; ks < 4; ks++) {
            const int k0 = ks * 16;
            uint32_t qf[4];
            ldA(qf, sb + AT_Q, wid * 16, k0, lane);
            #pragma unroll
            for (int np = 0; np < 4; np++) {
                uint32_t bf[4];
                ldB(bf, kof, np * 16, k0, lane);
                mmah(s[np * 2],     qf, bf[0], bf[1]);
                mmah(s[np * 2 + 1], qf, bf[2], bf[3]);
            }
        }

        // ---- online softmax, base 2 (MUFU ex2) ----
        float mx0 = -1e30f, mx1 = -1e30f;
        #pragma unroll
        for (int nt = 0; nt < 8; nt++) {
            mx0 = fmaxf(mx0, fmaxf(s[nt][0], s[nt][1]));
            mx1 = fmaxf(mx1, fmaxf(s[nt][2], s[nt][3]));
        }
        mx0 = rmax2(mx0);
        mx1 = rmax2(mx1);
        const float nm0 = fmaxf(mrow0, mx0), nm1 = fmaxf(mrow1, mx1);
        const float al0 = ex2(mrow0 - nm0), al1 = ex2(mrow1 - nm1);
        mrow0 = nm0; mrow1 = nm1;
        float sum0 = 0.f, sum1 = 0.f;
        #pragma unroll
        for (int nt = 0; nt < 8; nt++) {
            s[nt][0] = ex2(s[nt][0] - nm0);
            s[nt][1] = ex2(s[nt][1] - nm0);
            s[nt][2] = ex2(s[nt][2] - nm1);
            s[nt][3] = ex2(s[nt][3] - nm1);
            sum0 += s[nt][0] + s[nt][1];
            sum1 += s[nt][2] + s[nt][3];
        }
        lrow0 = lrow0 * al0 + rsum2(sum0);
        lrow1 = lrow1 * al1 + rsum2(sum1);
        #pragma unroll
        for (int nt = 0; nt < 8; nt++) {
            o[nt][0] *= al0; o[nt][1] *= al0;
            o[nt][2] *= al1; o[nt][3] *= al1;
        }

        // ---- O += P V, P straight from S accumulators (FA2 fragment reuse) --
        #pragma unroll
        for (int kc = 0; kc < 4; kc++) {
            uint32_t pf[4];
            pf[0] = packh2(s[2 * kc][0],     s[2 * kc][1]);
            pf[1] = packh2(s[2 * kc][2],     s[2 * kc][3]);
            pf[2] = packh2(s[2 * kc + 1][0], s[2 * kc + 1][1]);
            pf[3] = packh2(s[2 * kc + 1][2], s[2 * kc + 1][3]);
            #pragma unroll
            for (int np = 0; np < 4; np++) {
                uint32_t vf[4];
                ldVT(vf, vof, kc * 16, np * 16, lane);
                mmah(o[np * 2],     pf, vf[0], vf[1]);
                mmah(o[np * 2 + 1], pf, vf[2], vf[3]);
            }
        }
    }

    // ---- normalize + store ----
    const float i0 = 1.f / lrow0, i1 = 1.f / lrow1;
    const int q = q0 + wid * 16 + gid;
    float* dst0 = out + ((size_t)b * SEQ + q) * D_MODEL + h * 64;
    float* dst1 = dst0 + (size_t)8 * D_MODEL;
    #pragma unroll
    for (int nt = 0; nt < 8; nt++) {
        const int col = nt * 8 + 2 * tig;
        *(float2*)(dst0 + col) = make_float2(o[nt][0] * i0, o[nt][1] * i0);
        *(float2*)(dst1 + col) = make_float2(o[nt][2] * i1, o[nt][3] * i1);
    }
}

// ---------------------------------------------------------------------------
// Launch
// ---------------------------------------------------------------------------
extern "C" void kernel_launch(void* const* d_in, const int* in_sizes, int n_in,
                              void* d_out, int out_size)
{
    const float* q  = (const float*)d_in[0];
    const float* k  = (const float*)d_in[1];
    const float* v  = (const float*)d_in[2];
    const float* Wq = (const float*)d_in[3];
    const float* bq = (const float*)d_in[4];
    const float* Wk = (const float*)d_in[5];
    const float* bk = (const float*)d_in[6];
    const float* Wv = (const float*)d_in[7];
    const float* bv = (const float*)d_in[8];
    float* out = (float*)d_out;

    cudaFuncSetAttribute(proj_mma, cudaFuncAttributeMaxDynamicSharedMemorySize,
                         PJ_SMEM);
    cudaFuncSetAttribute(attn_mma, cudaFuncAttributeMaxDynamicSharedMemorySize,
                         AT_SMEM);

    dim3 gcv(IN_ELEMS / (256 * 4), 6);
    convert6<<<gcv, 256>>>(q, k, v, Wq, Wk, Wv);

    dim3 gproj(D_MODEL / 128, M_TOTAL / 128, 3);
    proj_mma<<<gproj, 256, PJ_SMEM>>>(bq, bk, bv);

    dim3 gattn(SEQ / 128, NUM_HEADS, BATCH);
    attn_mma<<<gattn, 256, AT_SMEM>>>(out);
}

// round 8
// speedup vs baseline: 7.4947x; 1.0601x over previous
#include <cuda_runtime.h>
#include <cuda_fp16.h>
#include <cstdint>

#define D_MODEL   512
#define NUM_HEADS 8
#define HEAD_DIM  64
#define SEQ       2048
#define BATCH     4
#define M_TOTAL   (BATCH * SEQ)          // 8192
#define IN_ELEMS  (M_TOTAL * D_MODEL)    // 4194304
#define W_ELEMS   (D_MODEL * D_MODEL)

// Q pre-scale: (1/sqrt(64)) * log2(e)  -> scores come out in log2 domain
#define QSCALE 0.1803368801111244f
#define ONES2  0x3C003C00u               // half2(1,1)

// ---------------------------------------------------------------------------
// Scratch
// ---------------------------------------------------------------------------
__device__ __half g_inh[3][IN_ELEMS];
__device__ __half g_Wh3[3][W_ELEMS];
// projected, head-major: idx = (h*M_TOTAL + m)*64 + d
__device__ __half g_Qh[IN_ELEMS], g_Kh[IN_ELEMS], g_Vh[IN_ELEMS];

// ---------------------------------------------------------------------------
// Helpers
// ---------------------------------------------------------------------------
__device__ __forceinline__ uint32_t smem_u32(const void* p) {
    uint32_t a;
    asm("{ .reg .u64 t; cvta.to.shared.u64 t, %1; cvt.u32.u64 %0, t; }"
        : "=r"(a) : "l"(p));
    return a;
}
__device__ __forceinline__ uint32_t swzo(int row, int col) {
    uint32_t bo = (uint32_t)row * 128u + (uint32_t)col * 2u;
    return bo ^ ((bo >> 3) & 0x70u);
}
#define LDSM4(R, a)                                                            \
    asm volatile("ldmatrix.sync.aligned.m8n8.x4.shared.b16 {%0,%1,%2,%3}, [%4];" \
        : "=r"((R)[0]), "=r"((R)[1]), "=r"((R)[2]), "=r"((R)[3]) : "r"(a))
#define LDSM4T(R, a)                                                           \
    asm volatile("ldmatrix.sync.aligned.m8n8.x4.trans.shared.b16 {%0,%1,%2,%3}, [%4];" \
        : "=r"((R)[0]), "=r"((R)[1]), "=r"((R)[2]), "=r"((R)[3]) : "r"(a))
#define CP16(dst, src)                                                         \
    asm volatile("cp.async.cg.shared.global [%0], [%1], 16;"                    \
                 :: "r"(dst), "l"(src) : "memory")
#define CP_COMMIT() asm volatile("cp.async.commit_group;" ::: "memory")
#define CP_WAIT(n)  asm volatile("cp.async.wait_group %0;" :: "n"(n) : "memory")

__device__ __forceinline__ void mmah(float* c, const uint32_t* a,
                                     uint32_t b0, uint32_t b1) {
    asm volatile(
        "mma.sync.aligned.m16n8k16.row.col.f32.f16.f16.f32 "
        "{%0,%1,%2,%3}, {%4,%5,%6,%7}, {%8,%9}, {%0,%1,%2,%3};"
        : "+f"(c[0]), "+f"(c[1]), "+f"(c[2]), "+f"(c[3])
        : "r"(a[0]), "r"(a[1]), "r"(a[2]), "r"(a[3]), "r"(b0), "r"(b1));
}
__device__ __forceinline__ void ldA(uint32_t R[4], uint32_t base, int row0,
                                    int k0, int lane) {
    LDSM4(R, base + swzo(row0 + (lane & 15), k0 + ((lane >> 4) << 3)));
}
__device__ __forceinline__ void ldB(uint32_t R[4], uint32_t base, int n0,
                                    int k0, int lane) {
    int g = lane >> 3;
    LDSM4(R, base + swzo(n0 + ((g >> 1) << 3) + (lane & 7), k0 + ((g & 1) << 3)));
}
__device__ __forceinline__ void ldVT(uint32_t R[4], uint32_t base, int k0,
                                     int n0, int lane) {
    int g = lane >> 3;
    LDSM4T(R, base + swzo(k0 + ((g & 1) << 3) + (lane & 7), n0 + ((g >> 1) << 3)));
}
// packed fp16 exp2: 2 elems per MUFU slot, result is ready-to-use P fragment
__device__ __forceinline__ uint32_t h2ex2(float a, float b) {
    __half2 h = __floats2half2_rn(a, b);
    uint32_t u = *(uint32_t*)&h, r;
    asm("ex2.approx.f16x2 %0, %1;" : "=r"(r) : "r"(u));
    return r;
}
__device__ __forceinline__ float ex2f(float x) {
    float r;
    asm("ex2.approx.f32 %0, %1;" : "=f"(r) : "f"(x));
    return r;
}

// ---------------------------------------------------------------------------
// Kernel 1: fp32 -> fp16 (8 elems/thread)
// ---------------------------------------------------------------------------
__global__ void convert6(const float* __restrict__ q, const float* __restrict__ k,
                         const float* __restrict__ v, const float* __restrict__ wq,
                         const float* __restrict__ wk, const float* __restrict__ wv)
{
    const int which = blockIdx.y;
    const float* src;
    __half* dh;
    int n;
    switch (which) {
        case 0: src = q;  dh = g_inh[0]; n = IN_ELEMS; break;
        case 1: src = k;  dh = g_inh[1]; n = IN_ELEMS; break;
        case 2: src = v;  dh = g_inh[2]; n = IN_ELEMS; break;
        case 3: src = wq; dh = g_Wh3[0]; n = W_ELEMS;  break;
        case 4: src = wk; dh = g_Wh3[1]; n = W_ELEMS;  break;
        default:src = wv; dh = g_Wh3[2]; n = W_ELEMS;  break;
    }
    int i = (blockIdx.x * 256 + threadIdx.x) * 8;
    if (i >= n) return;
    float4 x = *(const float4*)(src + i);
    float4 y = *(const float4*)(src + i + 4);
    __half2 a = __floats2half2_rn(x.x, x.y);
    __half2 b = __floats2half2_rn(x.z, x.w);
    __half2 c = __floats2half2_rn(y.x, y.y);
    __half2 d = __floats2half2_rn(y.z, y.w);
    uint4 o = make_uint4(*(uint32_t*)&a, *(uint32_t*)&b,
                         *(uint32_t*)&c, *(uint32_t*)&d);
    *(uint4*)(dh + i) = o;
}

// ---------------------------------------------------------------------------
// Kernel 2: projection GEMM  C = A @ W^T + b (fp16 HMMA, cp.async 2-stage)
// Block tile 128m x 128n, K-slab 64. 8 warps (2m x 4n). grid: (4, 64, 3)
// ---------------------------------------------------------------------------
#define PJ_A0 0
#define PJ_W0 16384
#define PJ_A1 32768
#define PJ_W1 49152
#define PJ_SMEM 65536

__device__ __forceinline__ void pj_issue(uint32_t sb, int buf,
                                         const __half* A, const __half* W,
                                         int m0g, int n0g, int kk, int tid) {
    const uint32_t aof = sb + (buf ? PJ_A1 : PJ_A0);
    const uint32_t wof = sb + (buf ? PJ_W1 : PJ_W0);
    #pragma unroll
    for (int it = 0; it < 4; it++) {
        int idx = tid + it * 256;            // 0..1023
        int r = idx >> 3, c = (idx & 7) * 8;
        uint32_t sw = swzo(r, c);
        CP16(aof + sw, A + (size_t)(m0g + r) * 512 + kk + c);
        CP16(wof + sw, W + (size_t)(n0g + r) * 512 + kk + c);
    }
}

__global__ __launch_bounds__(256)
void proj_mma(const float* __restrict__ bq, const float* __restrict__ bk,
              const float* __restrict__ bv)
{
    extern __shared__ char sm[];
    const uint32_t sb = smem_u32(sm);
    const int tid = threadIdx.x, lane = tid & 31, wid = tid >> 5;
    const int gid = lane >> 2, tig = lane & 3;
    const int wm = wid & 1, wn = wid >> 1;
    const int z = blockIdx.z;
    const int n0g = blockIdx.x * 128, m0g = blockIdx.y * 128;

    const __half* A = g_inh[z];
    const __half* W = g_Wh3[z];
    const float* bias = (z == 0) ? bq : (z == 1) ? bk : bv;
    __half* D = (z == 0) ? g_Qh : (z == 1) ? g_Kh : g_Vh;

    float acc[4][4][4];
    #pragma unroll
    for (int mt = 0; mt < 4; mt++)
        #pragma unroll
        for (int nt = 0; nt < 4; nt++)
            #pragma unroll
            for (int i = 0; i < 4; i++) acc[mt][nt][i] = 0.f;

    pj_issue(sb, 0, A, W, m0g, n0g, 0, tid);
    CP_COMMIT();

    for (int ks8 = 0; ks8 < 8; ks8++) {
        CP_WAIT(0);
        __syncthreads();
        if (ks8 + 1 < 8) {
            pj_issue(sb, (ks8 + 1) & 1, A, W, m0g, n0g, (ks8 + 1) * 64, tid);
            CP_COMMIT();
        }
        const uint32_t aof = sb + ((ks8 & 1) ? PJ_A1 : PJ_A0);
        const uint32_t wof = sb + ((ks8 & 1) ? PJ_W1 : PJ_W0);
        #pragma unroll
        for (int ks = 0; ks < 4; ks++) {
            const int k0 = ks * 16;
            uint32_t a[4][4], b[2][4];
            #pragma unroll
            for (int mt = 0; mt < 4; mt++)
                ldA(a[mt], aof, wm * 64 + mt * 16, k0, lane);
            #pragma unroll
            for (int np = 0; np < 2; np++)
                ldB(b[np], wof, wn * 32 + np * 16, k0, lane);
            #pragma unroll
            for (int mt = 0; mt < 4; mt++)
                #pragma unroll
                for (int np = 0; np < 2; np++) {
                    mmah(acc[mt][np * 2],     a[mt], b[np][0], b[np][1]);
                    mmah(acc[mt][np * 2 + 1], a[mt], b[np][2], b[np][3]);
                }
        }
    }

    // epilogue: +bias (Q also * QSCALE), store head-major fp16
    const float sc = (z == 0) ? QSCALE : 1.f;
    #pragma unroll
    for (int mt = 0; mt < 4; mt++) {
        #pragma unroll
        for (int nt = 0; nt < 4; nt++) {
            const int n = n0g + wn * 32 + nt * 8 + 2 * tig;
            const int h = n >> 6, d = n & 63;
            const float b0 = bias[n], b1 = bias[n + 1];
            #pragma unroll
            for (int half = 0; half < 2; half++) {
                const int m = m0g + wm * 64 + mt * 16 + gid + half * 8;
                __half2 hv = __floats2half2_rn(
                    (acc[mt][nt][half * 2]     + b0) * sc,
                    (acc[mt][nt][half * 2 + 1] + b1) * sc);
                *(uint32_t*)(D + ((size_t)h * M_TOTAL + m) * 64 + d) =
                    *(uint32_t*)&hv;
            }
        }
    }
}

// ---------------------------------------------------------------------------
// Kernel 3: fused flash attention
// fp16 HMMA; Q fragments hoisted; packed-fp16 ex2; row sums via ones-MMA.
// Block = 128 queries x 1 head, 8 warps. grid: (16, 8, 4)
// ---------------------------------------------------------------------------
#define AT_Q  0
#define AT_K0 16384
#define AT_V0 24576
#define AT_K1 32768
#define AT_V1 40960
#define AT_SMEM 49152
#define NTILES (SEQ / 64)

__device__ __forceinline__ void issue_kv(uint32_t sb, int buf,
                                         const __half* Kp, const __half* Vp,
                                         int tid) {
    const uint32_t kof = sb + AT_K0 + buf * 16384;
    const uint32_t vof = sb + AT_V0 + buf * 16384;
    #pragma unroll
    for (int it = 0; it < 2; it++) {
        int idx = tid + it * 256;                // 0..511
        int r = idx >> 3, c = (idx & 7) * 8;
        uint32_t sw = swzo(r, c);
        CP16(kof + sw, Kp + r * 64 + c);
        CP16(vof + sw, Vp + r * 64 + c);
    }
}

__global__ __launch_bounds__(256)
void attn_mma(float* __restrict__ out)
{
    extern __shared__ char sm[];
    const uint32_t sb = smem_u32(sm);
    const int tid = threadIdx.x, lane = tid & 31, wid = tid >> 5;
    const int gid = lane >> 2, tig = lane & 3;
    const int q0 = blockIdx.x * 128;
    const int h = blockIdx.y, b = blockIdx.z;

    const size_t qbase  = ((size_t)h * M_TOTAL + (size_t)b * SEQ + q0) * 64;
    const size_t kvbase = ((size_t)h * M_TOTAL + (size_t)b * SEQ) * 64;
    const __half* Kb = g_Kh + kvbase;
    const __half* Vb = g_Vh + kvbase;

    issue_kv(sb, 0, Kb, Vb, tid);
    CP_COMMIT();
    #pragma unroll
    for (int it = 0; it < 4; it++) {
        int idx = tid + it * 256;
        int r = idx >> 3, c = (idx & 7) * 8;
        *(uint4*)(sm + AT_Q + swzo(r, c)) =
            *(const uint4*)(g_Qh + qbase + r * 64 + c);
    }
    __syncthreads();   // Q staged (plain STS) before fragment loads

    // hoist loop-invariant Q fragments (16 regs)
    uint32_t qf[4][4];
    #pragma unroll
    for (int ks = 0; ks < 4; ks++)
        ldA(qf[ks], sb + AT_Q, wid * 16, ks * 16, lane);

    float o[8][4];
    #pragma unroll
    for (int nt = 0; nt < 8; nt++)
        #pragma unroll
        for (int i = 0; i < 4; i++) o[nt][i] = 0.f;
    float mrow0 = -1e30f, mrow1 = -1e30f, lrow0 = 0.f, lrow1 = 0.f;

    for (int kt = 0; kt < NTILES; kt++) {
        CP_WAIT(0);
        __syncthreads();
        if (kt + 1 < NTILES) {
            issue_kv(sb, (kt + 1) & 1, Kb + (kt + 1) * 4096,
                     Vb + (kt + 1) * 4096, tid);
            CP_COMMIT();
        }
        const uint32_t kof = sb + AT_K0 + (kt & 1) * 16384;
        const uint32_t vof = sb + AT_V0 + (kt & 1) * 16384;

        // ---- S = Q K^T (log2 domain) ----
        float s[8][4];
        #pragma unroll
        for (int nt = 0; nt < 8; nt++)
            #pragma unroll
            for (int i = 0; i < 4; i++) s[nt][i] = 0.f;

        #pragma unroll
        for (int ks = 0; ks < 4; ks++) {
            const int k0 = ks * 16;
            #pragma unroll
            for (int np = 0; np < 4; np++) {
                uint32_t bf[4];
                ldB(bf, kof, np * 16, k0, lane);
                mmah(s[np * 2],     qf[ks], bf[0], bf[1]);
                mmah(s[np * 2 + 1], qf[ks], bf[2], bf[3]);
            }
        }

        // ---- max (packed fp16 shfl reduction: 2 shfls for both rows) ----
        float mx0 = fmaxf(s[0][0], s[0][1]), mx1 = fmaxf(s[0][2], s[0][3]);
        #pragma unroll
        for (int nt = 1; nt < 8; nt++) {
            mx0 = fmaxf(mx0, fmaxf(s[nt][0], s[nt][1]));
            mx1 = fmaxf(mx1, fmaxf(s[nt][2], s[nt][3]));
        }
        __half2 m2 = __floats2half2_rn(mx0, mx1);
        uint32_t mu = *(uint32_t*)&m2;
        uint32_t t1 = __shfl_xor_sync(0xffffffffu, mu, 1);
        m2 = __hmax2(m2, *(__half2*)&t1);
        mu = *(uint32_t*)&m2;
        uint32_t t2 = __shfl_xor_sync(0xffffffffu, mu, 2);
        m2 = __hmax2(m2, *(__half2*)&t2);
        const float nm0 = fmaxf(mrow0, __low2float(m2));
        const float nm1 = fmaxf(mrow1, __high2float(m2));
        const float al0 = ex2f(mrow0 - nm0), al1 = ex2f(mrow1 - nm1);
        mrow0 = nm0; mrow1 = nm1;

        // ---- P fragments via packed fp16 ex2 ----
        uint32_t p[8][2];
        #pragma unroll
        for (int nt = 0; nt < 8; nt++) {
            p[nt][0] = h2ex2(s[nt][0] - nm0, s[nt][1] - nm0);
            p[nt][1] = h2ex2(s[nt][2] - nm1, s[nt][3] - nm1);
        }

        // ---- rescale O ----
        #pragma unroll
        for (int nt = 0; nt < 8; nt++) {
            o[nt][0] *= al0; o[nt][1] *= al0;
            o[nt][2] *= al1; o[nt][3] *= al1;
        }

        // ---- O += P V ; row sums via ones-column MMA ----
        float csum[4] = {0.f, 0.f, 0.f, 0.f};
        #pragma unroll
        for (int kc = 0; kc < 4; kc++) {
            uint32_t pf[4] = {p[2 * kc][0], p[2 * kc][1],
                              p[2 * kc + 1][0], p[2 * kc + 1][1]};
            mmah(csum, pf, ONES2, ONES2);
            #pragma unroll
            for (int np = 0; np < 4; np++) {
                uint32_t vf[4];
                ldVT(vf, vof, kc * 16, np * 16, lane);
                mmah(o[np * 2],     pf, vf[0], vf[1]);
                mmah(o[np * 2 + 1], pf, vf[2], vf[3]);
            }
        }
        lrow0 = lrow0 * al0 + csum[0];
        lrow1 = lrow1 * al1 + csum[2];
    }

    // ---- normalize + store ----
    const float i0 = 1.f / lrow0, i1 = 1.f / lrow1;
    const int q = q0 + wid * 16 + gid;
    float* dst0 = out + ((size_t)b * SEQ + q) * D_MODEL + h * 64;
    float* dst1 = dst0 + (size_t)8 * D_MODEL;
    #pragma unroll
    for (int nt = 0; nt < 8; nt++) {
        const int col = nt * 8 + 2 * tig;
        *(float2*)(dst0 + col) = make_float2(o[nt][0] * i0, o[nt][1] * i0);
        *(float2*)(dst1 + col) = make_float2(o[nt][2] * i1, o[nt][3] * i1);
    }
}

// ---------------------------------------------------------------------------
// Launch
// ---------------------------------------------------------------------------
extern "C" void kernel_launch(void* const* d_in, const int* in_sizes, int n_in,
                              void* d_out, int out_size)
{
    const float* q  = (const float*)d_in[0];
    const float* k  = (const float*)d_in[1];
    const float* v  = (const float*)d_in[2];
    const float* Wq = (const float*)d_in[3];
    const float* bq = (const float*)d_in[4];
    const float* Wk = (const float*)d_in[5];
    const float* bk = (const float*)d_in[6];
    const float* Wv = (const float*)d_in[7];
    const float* bv = (const float*)d_in[8];
    float* out = (float*)d_out;

    cudaFuncSetAttribute(proj_mma, cudaFuncAttributeMaxDynamicSharedMemorySize,
                         PJ_SMEM);
    cudaFuncSetAttribute(attn_mma, cudaFuncAttributeMaxDynamicSharedMemorySize,
                         AT_SMEM);

    dim3 gcv(IN_ELEMS / (256 * 8), 6);
    convert6<<<gcv, 256>>>(q, k, v, Wq, Wk, Wv);

    dim3 gproj(D_MODEL / 128, M_TOTAL / 128, 3);
    proj_mma<<<gproj, 256, PJ_SMEM>>>(bq, bk, bv);

    dim3 gattn(SEQ / 128, NUM_HEADS, BATCH);
    attn_mma<<<gattn, 256, AT_SMEM>>>(out);
}